// round 10
// baseline (speedup 1.0000x reference)
#include <cuda_runtime.h>
#include <cuda_bf16.h>
#include <cstdint>

#define S_LEN 4096
#define DM    768
#define NH    12
#define DK    64

// ---------------- scratch (device globals) ----------------
__device__ __nv_bfloat16 g_xh[S_LEN * DM],  g_xl[S_LEN * DM];
__device__ __nv_bfloat16 g_Wqh[DM * DM],    g_Wql[DM * DM];
__device__ __nv_bfloat16 g_Wkh[DM * DM],    g_Wkl[DM * DM];
__device__ __nv_bfloat16 g_Wvh[DM * DM],    g_Wvl[DM * DM];
__device__ __nv_bfloat16 g_Woh[DM * DM],    g_Wol[DM * DM];
__device__ __nv_bfloat16 g_Qh[S_LEN * DM],  g_Ql[S_LEN * DM];   // [s][hd]
__device__ __nv_bfloat16 g_Kh[S_LEN * DM],  g_Kl[S_LEN * DM];   // [s][hd]
__device__ __nv_bfloat16 g_Vth[DM * S_LEN], g_Vtl[DM * S_LEN];  // [hd][s]
__device__ __nv_bfloat16 g_ctxh[S_LEN * DM], g_ctxl[S_LEN * DM];

// ---------------- helpers ----------------
__device__ __forceinline__ uint32_t smem_u32(const void* p) {
    uint32_t a;
    asm("{ .reg .u64 t; cvta.to.shared.u64 t, %1; cvt.u32.u64 %0, t; }"
        : "=r"(a) : "l"(p));
    return a;
}
__device__ __forceinline__ void ldsm_x4(uint32_t* r, uint32_t addr) {
    asm volatile("ldmatrix.sync.aligned.m8n8.x4.shared.b16 {%0,%1,%2,%3}, [%4];"
                 : "=r"(r[0]), "=r"(r[1]), "=r"(r[2]), "=r"(r[3]) : "r"(addr));
}
__device__ __forceinline__ void mma_bf16(float* d, const uint32_t* a,
                                         uint32_t b0, uint32_t b1) {
    asm volatile("mma.sync.aligned.m16n8k16.row.col.f32.bf16.bf16.f32 "
                 "{%0,%1,%2,%3}, {%4,%5,%6,%7}, {%8,%9}, {%0,%1,%2,%3};"
                 : "+f"(d[0]), "+f"(d[1]), "+f"(d[2]), "+f"(d[3])
                 : "r"(a[0]), "r"(a[1]), "r"(a[2]), "r"(a[3]), "r"(b0), "r"(b1));
}
__device__ __forceinline__ void sts_v4(uint32_t addr, uint4 v) {
    asm volatile("st.shared.v4.b32 [%0], {%1, %2, %3, %4};"
                 :: "r"(addr), "r"(v.x), "r"(v.y), "r"(v.z), "r"(v.w) : "memory");
}
__device__ __forceinline__ void split2(float x, float y, uint32_t& hi, uint32_t& lo) {
    __nv_bfloat16 hx = __float2bfloat16(x), hy = __float2bfloat16(y);
    __nv_bfloat162 h2 = {hx, hy};
    hi = *(uint32_t*)&h2;
    __nv_bfloat162 l2 = {__float2bfloat16(x - __bfloat162float(hx)),
                         __float2bfloat16(y - __bfloat162float(hy))};
    lo = *(uint32_t*)&l2;
}
__device__ __forceinline__ void cp_async16(uint32_t dst, const void* src) {
    asm volatile("cp.async.cg.shared.global [%0], [%1], 16;"
                 :: "r"(dst), "l"(src));
}
#define CP_COMMIT() asm volatile("cp.async.commit_group;" ::: "memory")
#define CP_WAIT0()  asm volatile("cp.async.wait_group 0;" ::: "memory")
#define CP_WAIT1()  asm volatile("cp.async.wait_group 1;" ::: "memory")

// ---------------- single fp32 -> bf16 hi/lo split pass for all 5 tensors ----
#define NX4 (S_LEN * DM / 4)
#define NW4 (DM * DM / 4)

__global__ __launch_bounds__(256)
void split_all(const float* __restrict__ x,  const float* __restrict__ Wq,
               const float* __restrict__ Wk, const float* __restrict__ Wv,
               const float* __restrict__ Wo)
{
    int i = blockIdx.x * blockDim.x + threadIdx.x;
    const float* in;
    __nv_bfloat16 *hi, *lo;
    int j = i;
    if (j < NX4)            { in = x;  hi = g_xh;  lo = g_xl;  }
    else if ((j -= NX4) < NW4)   { in = Wq; hi = g_Wqh; lo = g_Wql; }
    else if ((j -= NW4) < NW4)   { in = Wk; hi = g_Wkh; lo = g_Wkl; }
    else if ((j -= NW4) < NW4)   { in = Wv; hi = g_Wvh; lo = g_Wvl; }
    else if ((j -= NW4) < NW4)   { in = Wo; hi = g_Woh; lo = g_Wol; }
    else return;
    float4 v = ((const float4*)in)[j];
    uint32_t h0, l0, h1, l1;
    split2(v.x, v.y, h0, l0);
    split2(v.z, v.w, h1, l1);
    ((uint2*)hi)[j] = make_uint2(h0, h1);
    ((uint2*)lo)[j] = make_uint2(l0, l1);
}

// ===========================================================================
// bf16x3 GEMM body: C = A[M,K] @ B[N,K]^T
// CTA tile 128x64, 256 threads (warp grid 4Mx2N, warp tile 32x32), BK=32,
// 3-stage cp.async pipeline, full per-chunk fragment hoisting.
// ===========================================================================
#define ROWB    80
#define TILE_A  (128 * ROWB)              // 10240
#define TILE_BB (64 * ROWB)               // 5120
#define BUF_B   (2 * TILE_A + 2 * TILE_BB) // 30720
#define AHI     0
#define ALO     TILE_A
#define BHI     (2 * TILE_A)
#define BLO     (2 * TILE_A + TILE_BB)
#define GEMM_SMEM (3 * BUF_B)             // 92160

template<int OMODE>
__device__ __forceinline__
void gemm_body64(const __nv_bfloat16* __restrict__ Ah, const __nv_bfloat16* __restrict__ Al,
                 const __nv_bfloat16* __restrict__ Bh, const __nv_bfloat16* __restrict__ Bl,
                 float* __restrict__ C,
                 __nv_bfloat16* __restrict__ Ch, __nv_bfloat16* __restrict__ Cl,
                 int M, int N, int K, int bm, int bn, uint32_t sbase)
{
    const int tid  = threadIdx.x;
    const int lane = tid & 31;
    const int warp = tid >> 5;
    const int m0 = (warp >> 1) * 32;
    const int n0 = (warp & 1) * 32;

    float acc[2][4][4];
    #pragma unroll
    for (int mt = 0; mt < 2; mt++)
        #pragma unroll
        for (int nf = 0; nf < 4; nf++)
            #pragma unroll
            for (int e = 0; e < 4; e++) acc[mt][nf][e] = 0.0f;

    const int nchunk = K / 32;

    auto issue = [&](int c) {
        const uint32_t buf = sbase + (uint32_t)(c % 3) * BUF_B;
        const int kc = c * 32;
        #pragma unroll
        for (int j = 0; j < 6; j++) {
            const int idx = tid + j * 256;
            uint32_t dst;
            const __nv_bfloat16* src;
            if (idx < 512) {
                const int row = idx >> 2, ch = idx & 3;
                dst = buf + AHI + row * ROWB + ch * 16;
                src = &Ah[(size_t)(bm + row) * K + kc + ch * 8];
            } else if (idx < 1024) {
                const int r2 = idx - 512;
                const int row = r2 >> 2, ch = r2 & 3;
                dst = buf + ALO + row * ROWB + ch * 16;
                src = &Al[(size_t)(bm + row) * K + kc + ch * 8];
            } else if (idx < 1280) {
                const int r2 = idx - 1024;
                const int row = r2 >> 2, ch = r2 & 3;
                dst = buf + BHI + row * ROWB + ch * 16;
                src = &Bh[(size_t)(bn + row) * K + kc + ch * 8];
            } else {
                const int r2 = idx - 1280;
                const int row = r2 >> 2, ch = r2 & 3;
                dst = buf + BLO + row * ROWB + ch * 16;
                src = &Bl[(size_t)(bn + row) * K + kc + ch * 8];
            }
            cp_async16(dst, src);
        }
        CP_COMMIT();
    };

    issue(0);
    issue(1);

    const uint32_t lrow = (lane & 15);
    const uint32_t koff = (lane >> 4) * 16;

    for (int c = 0; c < nchunk; ++c) {
        if (c + 1 < nchunk) { CP_WAIT1(); } else { CP_WAIT0(); }
        __syncthreads();                 // stage c visible; stage (c-1)%3 free
        if (c + 2 < nchunk) issue(c + 2);

        const uint32_t buf = sbase + (uint32_t)(c % 3) * BUF_B;

        // ---- hoist: load ALL fragments for both k16 steps first ----
        uint32_t ah[2][2][4], al[2][2][4];   // [ks][mt]
        uint32_t bh[2][2][4], bl[2][2][4];   // [ks][g]
        #pragma unroll
        for (int ks = 0; ks < 2; ks++) {
            const uint32_t kb = ks * 32 + koff;
            #pragma unroll
            for (int mt = 0; mt < 2; mt++) {
                const uint32_t ro = (uint32_t)(m0 + mt * 16 + lrow) * ROWB + kb;
                ldsm_x4(ah[ks][mt], buf + AHI + ro);
                ldsm_x4(al[ks][mt], buf + ALO + ro);
            }
            #pragma unroll
            for (int g = 0; g < 2; g++) {
                const uint32_t ro = (uint32_t)(n0 + g * 16 + lrow) * ROWB + kb;
                ldsm_x4(bh[ks][g], buf + BHI + ro);
                ldsm_x4(bl[ks][g], buf + BLO + ro);
            }
        }
        // ---- then all mma (same per-acc order as before -> bit-identical) ----
        #pragma unroll
        for (int ks = 0; ks < 2; ks++) {
            #pragma unroll
            for (int mt = 0; mt < 2; mt++) {
                #pragma unroll
                for (int g = 0; g < 2; g++) {
                    mma_bf16(acc[mt][g * 2 + 0], ah[ks][mt], bh[ks][g][0], bh[ks][g][2]);
                    mma_bf16(acc[mt][g * 2 + 0], ah[ks][mt], bl[ks][g][0], bl[ks][g][2]);
                    mma_bf16(acc[mt][g * 2 + 0], al[ks][mt], bh[ks][g][0], bh[ks][g][2]);
                    mma_bf16(acc[mt][g * 2 + 1], ah[ks][mt], bh[ks][g][1], bh[ks][g][3]);
                    mma_bf16(acc[mt][g * 2 + 1], ah[ks][mt], bl[ks][g][1], bl[ks][g][3]);
                    mma_bf16(acc[mt][g * 2 + 1], al[ks][mt], bh[ks][g][1], bh[ks][g][3]);
                }
            }
        }
    }

    #pragma unroll
    for (int mt = 0; mt < 2; mt++) {
        const int row = bm + m0 + mt * 16 + (lane >> 2);
        #pragma unroll
        for (int nf = 0; nf < 4; nf++) {
            const int col = bn + n0 + nf * 8 + (lane & 3) * 2;
            if (OMODE == 0) {
                *(float2*)&C[(size_t)row * N + col] =
                    make_float2(acc[mt][nf][0], acc[mt][nf][1]);
                *(float2*)&C[(size_t)(row + 8) * N + col] =
                    make_float2(acc[mt][nf][2], acc[mt][nf][3]);
            } else {
                uint32_t h0, l0, h1, l1;
                split2(acc[mt][nf][0], acc[mt][nf][1], h0, l0);
                split2(acc[mt][nf][2], acc[mt][nf][3], h1, l1);
                *(uint32_t*)&Ch[(size_t)row * N + col]       = h0;
                *(uint32_t*)&Cl[(size_t)row * N + col]       = l0;
                *(uint32_t*)&Ch[(size_t)(row + 8) * N + col] = h1;
                *(uint32_t*)&Cl[(size_t)(row + 8) * N + col] = l1;
            }
        }
    }
}

// Merged Q/K/V projection: grid (384, 3). Uniform 128x64 tiles.
__global__ __launch_bounds__(256, 2)
void gemm_qkv()
{
    extern __shared__ __align__(128) char dynsm[];
    const uint32_t sbase = smem_u32(dynsm);
    const int z  = blockIdx.y;
    const int bx = blockIdx.x;    // 0..383

    if (z == 0) {
        gemm_body64<1>(g_xh, g_xl, g_Wqh, g_Wql, nullptr, g_Qh, g_Ql,
                       S_LEN, DM, DM, (bx & 31) * 128, (bx >> 5) * 64, sbase);
    } else if (z == 1) {
        gemm_body64<1>(g_xh, g_xl, g_Wkh, g_Wkl, nullptr, g_Kh, g_Kl,
                       S_LEN, DM, DM, (bx & 31) * 128, (bx >> 5) * 64, sbase);
    } else {
        // V^T[hd][s] = Wv @ x^T : M=DM (6 tiles of 128), N=S_LEN (64 tiles of 64)
        gemm_body64<1>(g_Wvh, g_Wvl, g_xh, g_xl, nullptr, g_Vth, g_Vtl,
                       DM, S_LEN, DM, (bx % 6) * 128, (bx / 6) * 64, sbase);
    }
}

// Output projection: out = ctx @ Wo^T (fp32 out), grid (384)
__global__ __launch_bounds__(256, 2)
void gemm_out(float* __restrict__ out)
{
    extern __shared__ __align__(128) char dynsm[];
    const uint32_t sbase = smem_u32(dynsm);
    const int bx = blockIdx.x;
    gemm_body64<0>(g_ctxh, g_ctxl, g_Woh, g_Wol, out, nullptr, nullptr,
                   S_LEN, DM, DM, (bx & 31) * 128, (bx >> 5) * 64, sbase);
}

// ===========================================================================
// Tensor-core causal flash attention (bf16x3), cp.async double-buffered K/V.
// (unchanged from R9)
// ===========================================================================
#define AROWB 144
#define AQH   0
#define AQL   (128 * AROWB)
#define AKV   (2 * 128 * AROWB)
#define KVSTG 32768
#define KH_O  0
#define KL_O  8192
#define VH_O  16384
#define VL_O  24576
#define ATTN_SMEM (AKV + 2 * KVSTG)

__global__ __launch_bounds__(256, 2)
void attn_tc()
{
    extern __shared__ __align__(128) char dynbuf[];
    const uint32_t sb = smem_u32(dynbuf);

    const int tid  = threadIdx.x;
    const int lane = tid & 31;
    const int warp = tid >> 5;
    const int wr   = warp * 16;
    const int qb   = (int)gridDim.x - 1 - (int)blockIdx.x;
    const int h    = blockIdx.y;
    const int q0   = qb * 128;

    {
        const int gr = tid >> 3;
        const int gc = tid & 7;
        #pragma unroll
        for (int i = 0; i < 4; i++) {
            const int r = gr + i * 32;
            const uint32_t soff = (uint32_t)r * AROWB + gc * 16;
            uint4 vh = *(const uint4*)&g_Qh[(size_t)(q0 + r) * DM + h * 64 + gc * 8];
            uint4 vl = *(const uint4*)&g_Ql[(size_t)(q0 + r) * DM + h * 64 + gc * 8];
            sts_v4(sb + AQH + soff, vh);
            sts_v4(sb + AQL + soff, vl);
        }
    }

    auto issue_kv = [&](int t) {
        const uint32_t kvb = sb + AKV + (uint32_t)(t & 1) * KVSTG;
        const int k0 = t * 64;
        #pragma unroll
        for (int j = 0; j < 8; j++) {
            const int idx = tid + j * 256;
            const int arr = idx >> 9;
            const int rem = idx & 511;
            const int row = rem >> 3;
            const int c   = rem & 7;
            const uint32_t dst = kvb + (uint32_t)arr * 8192 + row * 128 +
                                 ((uint32_t)(c ^ (row & 7)) << 4);
            const __nv_bfloat16* src;
            if (arr == 0)      src = &g_Kh[(size_t)(k0 + row) * DM + h * 64 + c * 8];
            else if (arr == 1) src = &g_Kl[(size_t)(k0 + row) * DM + h * 64 + c * 8];
            else if (arr == 2) src = &g_Vth[(size_t)(h * 64 + row) * S_LEN + k0 + c * 8];
            else               src = &g_Vtl[(size_t)(h * 64 + row) * S_LEN + k0 + c * 8];
            cp_async16(dst, src);
        }
        CP_COMMIT();
    };

    issue_kv(0);

    float o[8][4];
    #pragma unroll
    for (int f = 0; f < 8; f++)
        #pragma unroll
        for (int e = 0; e < 4; e++) o[f][e] = 0.0f;
    float m_s[2] = {-1e30f, -1e30f};
    float l_s[2] = {0.0f, 0.0f};

    const int row0 = q0 + wr + (lane >> 2);
    const int row1 = row0 + 8;
    const uint32_t lrow = (lane & 15);
    const uint32_t koff = (lane >> 4) * 16;
    const int ntile = 2 * qb + 2;

    for (int t = 0; t < ntile; ++t) {
        const int k0 = t * 64;
        CP_WAIT0();
        __syncthreads();
        if (t + 1 < ntile) issue_kv(t + 1);

        const uint32_t kvb = sb + AKV + (uint32_t)(t & 1) * KVSTG;

        float sacc[8][4];
        #pragma unroll
        for (int f = 0; f < 8; f++)
            #pragma unroll
            for (int e = 0; e < 4; e++) sacc[f][e] = 0.0f;

        #pragma unroll
        for (int ks = 0; ks < 4; ks++) {
            uint32_t qh[4], ql[4];
            const uint32_t qoff = (uint32_t)(wr + lrow) * AROWB + ks * 32 + koff;
            ldsm_x4(qh, sb + AQH + qoff);
            ldsm_x4(ql, sb + AQL + qoff);
            const uint32_t cidx = ks * 2 + (lane >> 4);
            #pragma unroll
            for (int g = 0; g < 4; g++) {
                const uint32_t row = g * 16 + lrow;
                const uint32_t ro = row * 128 + ((cidx ^ (row & 7)) << 4);
                uint32_t kh[4], kl[4];
                ldsm_x4(kh, kvb + KH_O + ro);
                ldsm_x4(kl, kvb + KL_O + ro);
                mma_bf16(sacc[g * 2 + 0], qh, kh[0], kh[2]);
                mma_bf16(sacc[g * 2 + 0], qh, kl[0], kl[2]);
                mma_bf16(sacc[g * 2 + 0], ql, kh[0], kh[2]);
                mma_bf16(sacc[g * 2 + 1], qh, kh[1], kh[3]);
                mma_bf16(sacc[g * 2 + 1], qh, kl[1], kl[3]);
                mma_bf16(sacc[g * 2 + 1], ql, kh[1], kh[3]);
            }
        }

        const float scale = 0.125f;
        if (t >= 2 * qb) {
            #pragma unroll
            for (int f = 0; f < 8; f++) {
                const int cb = k0 + f * 8 + (lane & 3) * 2;
                sacc[f][0] = (cb     > row0) ? -1e30f : sacc[f][0] * scale;
                sacc[f][1] = (cb + 1 > row0) ? -1e30f : sacc[f][1] * scale;
                sacc[f][2] = (cb     > row1) ? -1e30f : sacc[f][2] * scale;
                sacc[f][3] = (cb + 1 > row1) ? -1e30f : sacc[f][3] * scale;
            }
        } else {
            #pragma unroll
            for (int f = 0; f < 8; f++)
                #pragma unroll
                for (int e = 0; e < 4; e++) sacc[f][e] *= scale;
        }

        float rm0 = -1e30f, rm1 = -1e30f;
        #pragma unroll
        for (int f = 0; f < 8; f++) {
            rm0 = fmaxf(rm0, fmaxf(sacc[f][0], sacc[f][1]));
            rm1 = fmaxf(rm1, fmaxf(sacc[f][2], sacc[f][3]));
        }
        #pragma unroll
        for (int off = 1; off < 4; off <<= 1) {
            rm0 = fmaxf(rm0, __shfl_xor_sync(0xffffffffu, rm0, off));
            rm1 = fmaxf(rm1, __shfl_xor_sync(0xffffffffu, rm1, off));
        }
        const float mn0 = fmaxf(m_s[0], rm0);
        const float mn1 = fmaxf(m_s[1], rm1);
        const float al0 = __expf(m_s[0] - mn0);
        const float al1 = __expf(m_s[1] - mn1);
        float rs0 = 0.0f, rs1 = 0.0f;
        #pragma unroll
        for (int f = 0; f < 8; f++) {
            sacc[f][0] = __expf(sacc[f][0] - mn0);
            sacc[f][1] = __expf(sacc[f][1] - mn0);
            sacc[f][2] = __expf(sacc[f][2] - mn1);
            sacc[f][3] = __expf(sacc[f][3] - mn1);
            rs0 += sacc[f][0] + sacc[f][1];
            rs1 += sacc[f][2] + sacc[f][3];
        }
        #pragma unroll
        for (int off = 1; off < 4; off <<= 1) {
            rs0 += __shfl_xor_sync(0xffffffffu, rs0, off);
            rs1 += __shfl_xor_sync(0xffffffffu, rs1, off);
        }
        l_s[0] = l_s[0] * al0 + rs0;
        l_s[1] = l_s[1] * al1 + rs1;
        m_s[0] = mn0;
        m_s[1] = mn1;
        #pragma unroll
        for (int f = 0; f < 8; f++) {
            o[f][0] *= al0; o[f][1] *= al0;
            o[f][2] *= al1; o[f][3] *= al1;
        }

        #pragma unroll
        for (int ks = 0; ks < 4; ks++) {
            const float* s0 = sacc[2 * ks];
            const float* s1 = sacc[2 * ks + 1];
            uint32_t ph[4], pl[4];
            split2(s0[0], s0[1], ph[0], pl[0]);
            split2(s0[2], s0[3], ph[1], pl[1]);
            split2(s1[0], s1[1], ph[2], pl[2]);
            split2(s1[2], s1[3], ph[3], pl[3]);
            const uint32_t cidx = ks * 2 + (lane >> 4);
            #pragma unroll
            for (int g = 0; g < 4; g++) {
                const uint32_t row = g * 16 + lrow;
                const uint32_t ro = row * 128 + ((cidx ^ (row & 7)) << 4);
                uint32_t vh[4], vl[4];
                ldsm_x4(vh, kvb + VH_O + ro);
                ldsm_x4(vl, kvb + VL_O + ro);
                mma_bf16(o[g * 2 + 0], ph, vh[0], vh[2]);
                mma_bf16(o[g * 2 + 0], pl, vh[0], vh[2]);
                mma_bf16(o[g * 2 + 0], ph, vl[0], vl[2]);
                mma_bf16(o[g * 2 + 1], ph, vh[1], vh[3]);
                mma_bf16(o[g * 2 + 1], pl, vh[1], vh[3]);
                mma_bf16(o[g * 2 + 1], ph, vl[1], vl[3]);
            }
        }
    }

    const float inv0 = 1.0f / l_s[0];
    const float inv1 = 1.0f / l_s[1];
    #pragma unroll
    for (int f = 0; f < 8; f++) {
        const int col = h * 64 + f * 8 + (lane & 3) * 2;
        uint32_t h0, l0, h1, l1;
        split2(o[f][0] * inv0, o[f][1] * inv0, h0, l0);
        split2(o[f][2] * inv1, o[f][3] * inv1, h1, l1);
        *(uint32_t*)&g_ctxh[(size_t)row0 * DM + col] = h0;
        *(uint32_t*)&g_ctxl[(size_t)row0 * DM + col] = l0;
        *(uint32_t*)&g_ctxh[(size_t)row1 * DM + col] = h1;
        *(uint32_t*)&g_ctxl[(size_t)row1 * DM + col] = l1;
    }
}

// ---------------------------------------------------------------------------
extern "C" void kernel_launch(void* const* d_in, const int* in_sizes, int n_in,
                              void* d_out, int out_size)
{
    const float* x  = (const float*)d_in[0];
    const float* Wq = (const float*)d_in[1];
    const float* Wk = (const float*)d_in[2];
    const float* Wv = (const float*)d_in[3];
    const float* Wo = (const float*)d_in[4];
    float* out = (float*)d_out;

    cudaFuncSetAttribute(gemm_qkv,
                         cudaFuncAttributeMaxDynamicSharedMemorySize, GEMM_SMEM);
    cudaFuncSetAttribute(gemm_out,
                         cudaFuncAttributeMaxDynamicSharedMemorySize, GEMM_SMEM);
    cudaFuncSetAttribute(attn_tc,
                         cudaFuncAttributeMaxDynamicSharedMemorySize, ATTN_SMEM);

    const int ntot4 = NX4 + 4 * NW4;
    split_all<<<(ntot4 + 255) / 256, 256>>>(x, Wq, Wk, Wv, Wo);

    gemm_qkv<<<dim3(384, 3), 256, GEMM_SMEM>>>();

    attn_tc<<<dim3(S_LEN / 128, NH), 256, ATTN_SMEM>>>();

    gemm_out<<<dim3(384), 256, GEMM_SMEM>>>(out);
}

// round 11
// speedup vs baseline: 1.1403x; 1.1403x over previous
#include <cuda_runtime.h>
#include <cuda_bf16.h>
#include <cstdint>

#define S_LEN 4096
#define DM    768
#define NH    12
#define DK    64

// ---------------- scratch (device globals) ----------------
__device__ __nv_bfloat16 g_xh[S_LEN * DM],  g_xl[S_LEN * DM];
__device__ __nv_bfloat16 g_Wqh[DM * DM],    g_Wql[DM * DM];
__device__ __nv_bfloat16 g_Wkh[DM * DM],    g_Wkl[DM * DM];
__device__ __nv_bfloat16 g_Wvh[DM * DM],    g_Wvl[DM * DM];
__device__ __nv_bfloat16 g_Woh[DM * DM],    g_Wol[DM * DM];
__device__ __nv_bfloat16 g_Qh[S_LEN * DM],  g_Ql[S_LEN * DM];   // [s][hd]
__device__ __nv_bfloat16 g_Kh[S_LEN * DM],  g_Kl[S_LEN * DM];   // [s][hd]
__device__ __nv_bfloat16 g_Vth[DM * S_LEN], g_Vtl[DM * S_LEN];  // [hd][s]
__device__ __nv_bfloat16 g_ctxh[S_LEN * DM], g_ctxl[S_LEN * DM];

// ---------------- helpers ----------------
__device__ __forceinline__ uint32_t smem_u32(const void* p) {
    uint32_t a;
    asm("{ .reg .u64 t; cvta.to.shared.u64 t, %1; cvt.u32.u64 %0, t; }"
        : "=r"(a) : "l"(p));
    return a;
}
__device__ __forceinline__ void ldsm_x4(uint32_t* r, uint32_t addr) {
    asm volatile("ldmatrix.sync.aligned.m8n8.x4.shared.b16 {%0,%1,%2,%3}, [%4];"
                 : "=r"(r[0]), "=r"(r[1]), "=r"(r[2]), "=r"(r[3]) : "r"(addr));
}
__device__ __forceinline__ void mma_bf16(float* d, const uint32_t* a,
                                         uint32_t b0, uint32_t b1) {
    asm volatile("mma.sync.aligned.m16n8k16.row.col.f32.bf16.bf16.f32 "
                 "{%0,%1,%2,%3}, {%4,%5,%6,%7}, {%8,%9}, {%0,%1,%2,%3};"
                 : "+f"(d[0]), "+f"(d[1]), "+f"(d[2]), "+f"(d[3])
                 : "r"(a[0]), "r"(a[1]), "r"(a[2]), "r"(a[3]), "r"(b0), "r"(b1));
}
__device__ __forceinline__ void sts_v4(uint32_t addr, uint4 v) {
    asm volatile("st.shared.v4.b32 [%0], {%1, %2, %3, %4};"
                 :: "r"(addr), "r"(v.x), "r"(v.y), "r"(v.z), "r"(v.w) : "memory");
}
__device__ __forceinline__ void split2(float x, float y, uint32_t& hi, uint32_t& lo) {
    __nv_bfloat16 hx = __float2bfloat16(x), hy = __float2bfloat16(y);
    __nv_bfloat162 h2 = {hx, hy};
    hi = *(uint32_t*)&h2;
    __nv_bfloat162 l2 = {__float2bfloat16(x - __bfloat162float(hx)),
                         __float2bfloat16(y - __bfloat162float(hy))};
    lo = *(uint32_t*)&l2;
}
__device__ __forceinline__ void cp_async16(uint32_t dst, const void* src) {
    asm volatile("cp.async.cg.shared.global [%0], [%1], 16;"
                 :: "r"(dst), "l"(src));
}
#define CP_COMMIT() asm volatile("cp.async.commit_group;" ::: "memory")
#define CP_WAIT0()  asm volatile("cp.async.wait_group 0;" ::: "memory")

// ---------------- single fp32 -> bf16 hi/lo split pass for all 5 tensors ----
#define NX4 (S_LEN * DM / 4)
#define NW4 (DM * DM / 4)

__global__ __launch_bounds__(256)
void split_all(const float* __restrict__ x,  const float* __restrict__ Wq,
               const float* __restrict__ Wk, const float* __restrict__ Wv,
               const float* __restrict__ Wo)
{
    int i = blockIdx.x * blockDim.x + threadIdx.x;
    const float* in;
    __nv_bfloat16 *hi, *lo;
    int j = i;
    if (j < NX4)            { in = x;  hi = g_xh;  lo = g_xl;  }
    else if ((j -= NX4) < NW4)   { in = Wq; hi = g_Wqh; lo = g_Wql; }
    else if ((j -= NW4) < NW4)   { in = Wk; hi = g_Wkh; lo = g_Wkl; }
    else if ((j -= NW4) < NW4)   { in = Wv; hi = g_Wvh; lo = g_Wvl; }
    else if ((j -= NW4) < NW4)   { in = Wo; hi = g_Woh; lo = g_Wol; }
    else return;
    float4 v = ((const float4*)in)[j];
    uint32_t h0, l0, h1, l1;
    split2(v.x, v.y, h0, l0);
    split2(v.z, v.w, h1, l1);
    ((uint2*)hi)[j] = make_uint2(h0, h1);
    ((uint2*)lo)[j] = make_uint2(l0, l1);
}

// ===========================================================================
// bf16x3 GEMM body: C = A[M,K] @ B[N,K]^T  (R9 configuration)
// CTA tile 128 x BNR, 256 threads, BK=32, cp.async double buffer.
// ===========================================================================
#define ROWB      80
#define TILE_A    (128 * ROWB)

template<int OMODE, int BNR>
__device__ __forceinline__
void gemm_body(const __nv_bfloat16* __restrict__ Ah, const __nv_bfloat16* __restrict__ Al,
               const __nv_bfloat16* __restrict__ Bh, const __nv_bfloat16* __restrict__ Bl,
               float* __restrict__ C,
               __nv_bfloat16* __restrict__ Ch, __nv_bfloat16* __restrict__ Cl,
               int M, int N, int K, int bm, int bn, uint32_t sbase)
{
    constexpr int TILE_BB = BNR * ROWB;
    constexpr int BUF_B   = 2 * TILE_A + 2 * TILE_BB;
    constexpr int AHI = 0, ALO = TILE_A, BHI = 2 * TILE_A, BLO = 2 * TILE_A + TILE_BB;
    constexpr int NF = BNR / 16;
    constexpr int NCP = (1024 + BNR * 8) / 256;

    const int tid  = threadIdx.x;
    const int lane = tid & 31;
    const int warp = tid >> 5;
    const int m0 = (warp >> 1) * 32;
    const int n0 = (warp & 1) * (BNR / 2);

    float acc[2][NF][4];
    #pragma unroll
    for (int mt = 0; mt < 2; mt++)
        #pragma unroll
        for (int nf = 0; nf < NF; nf++)
            #pragma unroll
            for (int e = 0; e < 4; e++) acc[mt][nf][e] = 0.0f;

    const int nchunk = K / 32;

    auto issue = [&](int c) {
        const uint32_t buf = sbase + (uint32_t)(c & 1) * BUF_B;
        const int kc = c * 32;
        #pragma unroll
        for (int j = 0; j < NCP; j++) {
            const int idx = tid + j * 256;
            uint32_t dst;
            const __nv_bfloat16* src;
            if (idx < 512) {
                const int row = idx >> 2, ch = idx & 3;
                dst = buf + AHI + row * ROWB + ch * 16;
                src = &Ah[(size_t)(bm + row) * K + kc + ch * 8];
            } else if (idx < 1024) {
                const int r2 = idx - 512;
                const int row = r2 >> 2, ch = r2 & 3;
                dst = buf + ALO + row * ROWB + ch * 16;
                src = &Al[(size_t)(bm + row) * K + kc + ch * 8];
            } else if (idx < 1024 + BNR * 4) {
                const int r2 = idx - 1024;
                const int row = r2 >> 2, ch = r2 & 3;
                dst = buf + BHI + row * ROWB + ch * 16;
                src = &Bh[(size_t)(bn + row) * K + kc + ch * 8];
            } else {
                const int r2 = idx - (1024 + BNR * 4);
                const int row = r2 >> 2, ch = r2 & 3;
                dst = buf + BLO + row * ROWB + ch * 16;
                src = &Bl[(size_t)(bn + row) * K + kc + ch * 8];
            }
            cp_async16(dst, src);
        }
        CP_COMMIT();
    };

    issue(0);

    const uint32_t lrow = (lane & 15);
    const uint32_t koff = (lane >> 4) * 16;

    for (int c = 0; c < nchunk; ++c) {
        CP_WAIT0();
        __syncthreads();
        if (c + 1 < nchunk) issue(c + 1);

        const uint32_t buf = sbase + (uint32_t)(c & 1) * BUF_B;
        #pragma unroll
        for (int ks = 0; ks < 2; ks++) {
            const uint32_t kb = ks * 32 + koff;
            uint32_t ah[2][4], al[2][4];
            #pragma unroll
            for (int mt = 0; mt < 2; mt++) {
                const uint32_t ro = (uint32_t)(m0 + mt * 16 + lrow) * ROWB + kb;
                ldsm_x4(ah[mt], buf + AHI + ro);
                ldsm_x4(al[mt], buf + ALO + ro);
            }
            uint32_t bh[NF / 2][4], bl[NF / 2][4];
            #pragma unroll
            for (int g = 0; g < NF / 2; g++) {
                const uint32_t ro = (uint32_t)(n0 + g * 16 + lrow) * ROWB + kb;
                ldsm_x4(bh[g], buf + BHI + ro);
                ldsm_x4(bl[g], buf + BLO + ro);
            }
            #pragma unroll
            for (int mt = 0; mt < 2; mt++) {
                #pragma unroll
                for (int g = 0; g < NF / 2; g++) {
                    mma_bf16(acc[mt][g * 2 + 0], ah[mt], bh[g][0], bh[g][2]);
                    mma_bf16(acc[mt][g * 2 + 0], ah[mt], bl[g][0], bl[g][2]);
                    mma_bf16(acc[mt][g * 2 + 0], al[mt], bh[g][0], bh[g][2]);
                    mma_bf16(acc[mt][g * 2 + 1], ah[mt], bh[g][1], bh[g][3]);
                    mma_bf16(acc[mt][g * 2 + 1], ah[mt], bl[g][1], bl[g][3]);
                    mma_bf16(acc[mt][g * 2 + 1], al[mt], bh[g][1], bh[g][3]);
                }
            }
        }
        __syncthreads();
    }

    #pragma unroll
    for (int mt = 0; mt < 2; mt++) {
        const int row = bm + m0 + mt * 16 + (lane >> 2);
        #pragma unroll
        for (int nf = 0; nf < NF; nf++) {
            const int col = bn + n0 + nf * 8 + (lane & 3) * 2;
            if (OMODE == 0) {
                *(float2*)&C[(size_t)row * N + col] =
                    make_float2(acc[mt][nf][0], acc[mt][nf][1]);
                *(float2*)&C[(size_t)(row + 8) * N + col] =
                    make_float2(acc[mt][nf][2], acc[mt][nf][3]);
            } else {
                uint32_t h0, l0, h1, l1;
                split2(acc[mt][nf][0], acc[mt][nf][1], h0, l0);
                split2(acc[mt][nf][2], acc[mt][nf][3], h1, l1);
                *(uint32_t*)&Ch[(size_t)row * N + col]       = h0;
                *(uint32_t*)&Cl[(size_t)row * N + col]       = l0;
                *(uint32_t*)&Ch[(size_t)(row + 8) * N + col] = h1;
                *(uint32_t*)&Cl[(size_t)(row + 8) * N + col] = l1;
            }
        }
    }
}

#define GEMM_SMEM_128 (2 * (2 * TILE_A + 2 * 128 * ROWB))   // 81920
#define GEMM_SMEM_64  (2 * (2 * TILE_A + 2 * 64 * ROWB))    // 61440

// Merged Q/K/V projection: grid (32, 6, 3); z selects operand set.
__global__ __launch_bounds__(256, 2)
void gemm_qkv()
{
    extern __shared__ __align__(128) char dynsm[];
    const uint32_t sbase = smem_u32(dynsm);
    const int z = blockIdx.z;

    if (z == 0) {
        gemm_body<1, 128>(g_xh, g_xl, g_Wqh, g_Wql, nullptr, g_Qh, g_Ql,
                          S_LEN, DM, DM, blockIdx.x * 128, blockIdx.y * 128, sbase);
    } else if (z == 1) {
        gemm_body<1, 128>(g_xh, g_xl, g_Wkh, g_Wkl, nullptr, g_Kh, g_Kl,
                          S_LEN, DM, DM, blockIdx.x * 128, blockIdx.y * 128, sbase);
    } else {
        // V^T[hd][s] = Wv @ x^T : swap tile roles
        gemm_body<1, 128>(g_Wvh, g_Wvl, g_xh, g_xl, nullptr, g_Vth, g_Vtl,
                          DM, S_LEN, DM, blockIdx.y * 128, blockIdx.x * 128, sbase);
    }
}

// Output projection: out = ctx @ Wo^T (fp32 out), 128x64 tiles, grid (32, 12)
__global__ __launch_bounds__(256, 2)
void gemm_out(float* __restrict__ out)
{
    extern __shared__ __align__(128) char dynsm[];
    const uint32_t sbase = smem_u32(dynsm);
    gemm_body<0, 64>(g_ctxh, g_ctxl, g_Woh, g_Wol, out, nullptr, nullptr,
                     S_LEN, DM, DM, blockIdx.x * 128, blockIdx.y * 64, sbase);
}

// ===========================================================================
// Tensor-core causal flash attention (bf16x3), cp.async double-buffered K/V.
// 1-D grid with global LPT order: heaviest (qb=31) CTAs of ALL heads first.
// ===========================================================================
#define AROWB 144
#define AQH   0
#define AQL   (128 * AROWB)
#define AKV   (2 * 128 * AROWB)
#define KVSTG 32768
#define KH_O  0
#define KL_O  8192
#define VH_O  16384
#define VL_O  24576
#define ATTN_SMEM (AKV + 2 * KVSTG)

__global__ __launch_bounds__(256, 2)
void attn_tc()
{
    extern __shared__ __align__(128) char dynbuf[];
    const uint32_t sb = smem_u32(dynbuf);

    const int tid  = threadIdx.x;
    const int lane = tid & 31;
    const int warp = tid >> 5;
    const int wr   = warp * 16;
    // Global LPT: bid 0..11 -> qb=31 (all heads), bid 12..23 -> qb=30, ...
    const int rank = blockIdx.x;
    const int qb   = (S_LEN / 128) - 1 - rank / NH;
    const int h    = rank % NH;
    const int q0   = qb * 128;

    {
        const int gr = tid >> 3;
        const int gc = tid & 7;
        #pragma unroll
        for (int i = 0; i < 4; i++) {
            const int r = gr + i * 32;
            const uint32_t soff = (uint32_t)r * AROWB + gc * 16;
            uint4 vh = *(const uint4*)&g_Qh[(size_t)(q0 + r) * DM + h * 64 + gc * 8];
            uint4 vl = *(const uint4*)&g_Ql[(size_t)(q0 + r) * DM + h * 64 + gc * 8];
            sts_v4(sb + AQH + soff, vh);
            sts_v4(sb + AQL + soff, vl);
        }
    }

    auto issue_kv = [&](int t) {
        const uint32_t kvb = sb + AKV + (uint32_t)(t & 1) * KVSTG;
        const int k0 = t * 64;
        #pragma unroll
        for (int j = 0; j < 8; j++) {
            const int idx = tid + j * 256;
            const int arr = idx >> 9;
            const int rem = idx & 511;
            const int row = rem >> 3;
            const int c   = rem & 7;
            const uint32_t dst = kvb + (uint32_t)arr * 8192 + row * 128 +
                                 ((uint32_t)(c ^ (row & 7)) << 4);
            const __nv_bfloat16* src;
            if (arr == 0)      src = &g_Kh[(size_t)(k0 + row) * DM + h * 64 + c * 8];
            else if (arr == 1) src = &g_Kl[(size_t)(k0 + row) * DM + h * 64 + c * 8];
            else if (arr == 2) src = &g_Vth[(size_t)(h * 64 + row) * S_LEN + k0 + c * 8];
            else               src = &g_Vtl[(size_t)(h * 64 + row) * S_LEN + k0 + c * 8];
            cp_async16(dst, src);
        }
        CP_COMMIT();
    };

    issue_kv(0);

    float o[8][4];
    #pragma unroll
    for (int f = 0; f < 8; f++)
        #pragma unroll
        for (int e = 0; e < 4; e++) o[f][e] = 0.0f;
    float m_s[2] = {-1e30f, -1e30f};
    float l_s[2] = {0.0f, 0.0f};

    const int row0 = q0 + wr + (lane >> 2);
    const int row1 = row0 + 8;
    const uint32_t lrow = (lane & 15);
    const uint32_t koff = (lane >> 4) * 16;
    const int ntile = 2 * qb + 2;

    for (int t = 0; t < ntile; ++t) {
        const int k0 = t * 64;
        CP_WAIT0();
        __syncthreads();
        if (t + 1 < ntile) issue_kv(t + 1);

        const uint32_t kvb = sb + AKV + (uint32_t)(t & 1) * KVSTG;

        float sacc[8][4];
        #pragma unroll
        for (int f = 0; f < 8; f++)
            #pragma unroll
            for (int e = 0; e < 4; e++) sacc[f][e] = 0.0f;

        #pragma unroll
        for (int ks = 0; ks < 4; ks++) {
            uint32_t qh[4], ql[4];
            const uint32_t qoff = (uint32_t)(wr + lrow) * AROWB + ks * 32 + koff;
            ldsm_x4(qh, sb + AQH + qoff);
            ldsm_x4(ql, sb + AQL + qoff);
            const uint32_t cidx = ks * 2 + (lane >> 4);
            #pragma unroll
            for (int g = 0; g < 4; g++) {
                const uint32_t row = g * 16 + lrow;
                const uint32_t ro = row * 128 + ((cidx ^ (row & 7)) << 4);
                uint32_t kh[4], kl[4];
                ldsm_x4(kh, kvb + KH_O + ro);
                ldsm_x4(kl, kvb + KL_O + ro);
                mma_bf16(sacc[g * 2 + 0], qh, kh[0], kh[2]);
                mma_bf16(sacc[g * 2 + 0], qh, kl[0], kl[2]);
                mma_bf16(sacc[g * 2 + 0], ql, kh[0], kh[2]);
                mma_bf16(sacc[g * 2 + 1], qh, kh[1], kh[3]);
                mma_bf16(sacc[g * 2 + 1], qh, kl[1], kl[3]);
                mma_bf16(sacc[g * 2 + 1], ql, kh[1], kh[3]);
            }
        }

        const float scale = 0.125f;
        if (t >= 2 * qb) {
            #pragma unroll
            for (int f = 0; f < 8; f++) {
                const int cb = k0 + f * 8 + (lane & 3) * 2;
                sacc[f][0] = (cb     > row0) ? -1e30f : sacc[f][0] * scale;
                sacc[f][1] = (cb + 1 > row0) ? -1e30f : sacc[f][1] * scale;
                sacc[f][2] = (cb     > row1) ? -1e30f : sacc[f][2] * scale;
                sacc[f][3] = (cb + 1 > row1) ? -1e30f : sacc[f][3] * scale;
            }
        } else {
            #pragma unroll
            for (int f = 0; f < 8; f++)
                #pragma unroll
                for (int e = 0; e < 4; e++) sacc[f][e] *= scale;
        }

        float rm0 = -1e30f, rm1 = -1e30f;
        #pragma unroll
        for (int f = 0; f < 8; f++) {
            rm0 = fmaxf(rm0, fmaxf(sacc[f][0], sacc[f][1]));
            rm1 = fmaxf(rm1, fmaxf(sacc[f][2], sacc[f][3]));
        }
        #pragma unroll
        for (int off = 1; off < 4; off <<= 1) {
            rm0 = fmaxf(rm0, __shfl_xor_sync(0xffffffffu, rm0, off));
            rm1 = fmaxf(rm1, __shfl_xor_sync(0xffffffffu, rm1, off));
        }
        const float mn0 = fmaxf(m_s[0], rm0);
        const float mn1 = fmaxf(m_s[1], rm1);
        const float al0 = __expf(m_s[0] - mn0);
        const float al1 = __expf(m_s[1] - mn1);
        float rs0 = 0.0f, rs1 = 0.0f;
        #pragma unroll
        for (int f = 0; f < 8; f++) {
            sacc[f][0] = __expf(sacc[f][0] - mn0);
            sacc[f][1] = __expf(sacc[f][1] - mn0);
            sacc[f][2] = __expf(sacc[f][2] - mn1);
            sacc[f][3] = __expf(sacc[f][3] - mn1);
            rs0 += sacc[f][0] + sacc[f][1];
            rs1 += sacc[f][2] + sacc[f][3];
        }
        #pragma unroll
        for (int off = 1; off < 4; off <<= 1) {
            rs0 += __shfl_xor_sync(0xffffffffu, rs0, off);
            rs1 += __shfl_xor_sync(0xffffffffu, rs1, off);
        }
        l_s[0] = l_s[0] * al0 + rs0;
        l_s[1] = l_s[1] * al1 + rs1;
        m_s[0] = mn0;
        m_s[1] = mn1;
        #pragma unroll
        for (int f = 0; f < 8; f++) {
            o[f][0] *= al0; o[f][1] *= al0;
            o[f][2] *= al1; o[f][3] *= al1;
        }

        #pragma unroll
        for (int ks = 0; ks < 4; ks++) {
            const float* s0 = sacc[2 * ks];
            const float* s1 = sacc[2 * ks + 1];
            uint32_t ph[4], pl[4];
            split2(s0[0], s0[1], ph[0], pl[0]);
            split2(s0[2], s0[3], ph[1], pl[1]);
            split2(s1[0], s1[1], ph[2], pl[2]);
            split2(s1[2], s1[3], ph[3], pl[3]);
            const uint32_t cidx = ks * 2 + (lane >> 4);
            #pragma unroll
            for (int g = 0; g < 4; g++) {
                const uint32_t row = g * 16 + lrow;
                const uint32_t ro = row * 128 + ((cidx ^ (row & 7)) << 4);
                uint32_t vh[4], vl[4];
                ldsm_x4(vh, kvb + VH_O + ro);
                ldsm_x4(vl, kvb + VL_O + ro);
                mma_bf16(o[g * 2 + 0], ph, vh[0], vh[2]);
                mma_bf16(o[g * 2 + 0], pl, vh[0], vh[2]);
                mma_bf16(o[g * 2 + 0], ph, vl[0], vl[2]);
                mma_bf16(o[g * 2 + 1], ph, vh[1], vh[3]);
                mma_bf16(o[g * 2 + 1], pl, vh[1], vh[3]);
                mma_bf16(o[g * 2 + 1], ph, vl[1], vl[3]);
            }
        }
    }

    const float inv0 = 1.0f / l_s[0];
    const float inv1 = 1.0f / l_s[1];
    #pragma unroll
    for (int f = 0; f < 8; f++) {
        const int col = h * 64 + f * 8 + (lane & 3) * 2;
        uint32_t h0, l0, h1, l1;
        split2(o[f][0] * inv0, o[f][1] * inv0, h0, l0);
        split2(o[f][2] * inv1, o[f][3] * inv1, h1, l1);
        *(uint32_t*)&g_ctxh[(size_t)row0 * DM + col] = h0;
        *(uint32_t*)&g_ctxl[(size_t)row0 * DM + col] = l0;
        *(uint32_t*)&g_ctxh[(size_t)row1 * DM + col] = h1;
        *(uint32_t*)&g_ctxl[(size_t)row1 * DM + col] = l1;
    }
}

// ---------------------------------------------------------------------------
extern "C" void kernel_launch(void* const* d_in, const int* in_sizes, int n_in,
                              void* d_out, int out_size)
{
    const float* x  = (const float*)d_in[0];
    const float* Wq = (const float*)d_in[1];
    const float* Wk = (const float*)d_in[2];
    const float* Wv = (const float*)d_in[3];
    const float* Wo = (const float*)d_in[4];
    float* out = (float*)d_out;

    cudaFuncSetAttribute(gemm_qkv,
                         cudaFuncAttributeMaxDynamicSharedMemorySize, GEMM_SMEM_128);
    cudaFuncSetAttribute(gemm_out,
                         cudaFuncAttributeMaxDynamicSharedMemorySize, GEMM_SMEM_64);
    cudaFuncSetAttribute(attn_tc,
                         cudaFuncAttributeMaxDynamicSharedMemorySize, ATTN_SMEM);

    const int ntot4 = NX4 + 4 * NW4;
    split_all<<<(ntot4 + 255) / 256, 256>>>(x, Wq, Wk, Wv, Wo);

    gemm_qkv<<<dim3(S_LEN / 128, DM / 128, 3), 256, GEMM_SMEM_128>>>();

    attn_tc<<<dim3((S_LEN / 128) * NH), 256, ATTN_SMEM>>>();

    gemm_out<<<dim3(S_LEN / 128, DM / 64), 256, GEMM_SMEM_64>>>(out);
}

// round 12
// speedup vs baseline: 1.3597x; 1.1925x over previous
#include <cuda_runtime.h>
#include <cuda_bf16.h>
#include <cuda_fp16.h>
#include <cstdint>

#define S_LEN 4096
#define DM    768
#define NH    12
#define DK    64

// ---------------- scratch (device globals) ----------------
__device__ __nv_bfloat16 g_xh[S_LEN * DM],  g_xl[S_LEN * DM];
__device__ __nv_bfloat16 g_Wqh[DM * DM],    g_Wql[DM * DM];
__device__ __nv_bfloat16 g_Wkh[DM * DM],    g_Wkl[DM * DM];
__device__ __nv_bfloat16 g_Wvh[DM * DM],    g_Wvl[DM * DM];
__device__ __nv_bfloat16 g_Woh[DM * DM],    g_Wol[DM * DM];
__device__ __nv_bfloat16 g_Qh[S_LEN * DM],  g_Ql[S_LEN * DM];   // [s][hd]
__device__ __nv_bfloat16 g_Kh[S_LEN * DM],  g_Kl[S_LEN * DM];   // [s][hd]
__device__ __half        g_Vt[DM * S_LEN];                      // [hd][s], fp16
__device__ __nv_bfloat16 g_ctxh[S_LEN * DM], g_ctxl[S_LEN * DM];

// ---------------- helpers ----------------
__device__ __forceinline__ uint32_t smem_u32(const void* p) {
    uint32_t a;
    asm("{ .reg .u64 t; cvta.to.shared.u64 t, %1; cvt.u32.u64 %0, t; }"
        : "=r"(a) : "l"(p));
    return a;
}
__device__ __forceinline__ void ldsm_x4(uint32_t* r, uint32_t addr) {
    asm volatile("ldmatrix.sync.aligned.m8n8.x4.shared.b16 {%0,%1,%2,%3}, [%4];"
                 : "=r"(r[0]), "=r"(r[1]), "=r"(r[2]), "=r"(r[3]) : "r"(addr));
}
__device__ __forceinline__ void mma_bf16(float* d, const uint32_t* a,
                                         uint32_t b0, uint32_t b1) {
    asm volatile("mma.sync.aligned.m16n8k16.row.col.f32.bf16.bf16.f32 "
                 "{%0,%1,%2,%3}, {%4,%5,%6,%7}, {%8,%9}, {%0,%1,%2,%3};"
                 : "+f"(d[0]), "+f"(d[1]), "+f"(d[2]), "+f"(d[3])
                 : "r"(a[0]), "r"(a[1]), "r"(a[2]), "r"(a[3]), "r"(b0), "r"(b1));
}
__device__ __forceinline__ void mma_fp16(float* d, const uint32_t* a,
                                         uint32_t b0, uint32_t b1) {
    asm volatile("mma.sync.aligned.m16n8k16.row.col.f32.f16.f16.f32 "
                 "{%0,%1,%2,%3}, {%4,%5,%6,%7}, {%8,%9}, {%0,%1,%2,%3};"
                 : "+f"(d[0]), "+f"(d[1]), "+f"(d[2]), "+f"(d[3])
                 : "r"(a[0]), "r"(a[1]), "r"(a[2]), "r"(a[3]), "r"(b0), "r"(b1));
}
__device__ __forceinline__ void sts_v4(uint32_t addr, uint4 v) {
    asm volatile("st.shared.v4.b32 [%0], {%1, %2, %3, %4};"
                 :: "r"(addr), "r"(v.x), "r"(v.y), "r"(v.z), "r"(v.w) : "memory");
}
__device__ __forceinline__ void split2(float x, float y, uint32_t& hi, uint32_t& lo) {
    __nv_bfloat16 hx = __float2bfloat16(x), hy = __float2bfloat16(y);
    __nv_bfloat162 h2 = {hx, hy};
    hi = *(uint32_t*)&h2;
    __nv_bfloat162 l2 = {__float2bfloat16(x - __bfloat162float(hx)),
                         __float2bfloat16(y - __bfloat162float(hy))};
    lo = *(uint32_t*)&l2;
}
__device__ __forceinline__ uint32_t pack_h2(float x, float y) {
    __half2 h = __floats2half2_rn(x, y);
    return *(uint32_t*)&h;
}
__device__ __forceinline__ float round_h(float x) {
    return __half2float(__float2half_rn(x));
}
__device__ __forceinline__ void cp_async16(uint32_t dst, const void* src) {
    asm volatile("cp.async.cg.shared.global [%0], [%1], 16;"
                 :: "r"(dst), "l"(src));
}
#define CP_COMMIT() asm volatile("cp.async.commit_group;" ::: "memory")
#define CP_WAIT0()  asm volatile("cp.async.wait_group 0;" ::: "memory")

// ---------------- single fp32 -> bf16 hi/lo split pass for all 5 tensors ----
#define NX4 (S_LEN * DM / 4)
#define NW4 (DM * DM / 4)

__global__ __launch_bounds__(256)
void split_all(const float* __restrict__ x,  const float* __restrict__ Wq,
               const float* __restrict__ Wk, const float* __restrict__ Wv,
               const float* __restrict__ Wo)
{
    int i = blockIdx.x * blockDim.x + threadIdx.x;
    const float* in;
    __nv_bfloat16 *hi, *lo;
    int j = i;
    if (j < NX4)            { in = x;  hi = g_xh;  lo = g_xl;  }
    else if ((j -= NX4) < NW4)   { in = Wq; hi = g_Wqh; lo = g_Wql; }
    else if ((j -= NW4) < NW4)   { in = Wk; hi = g_Wkh; lo = g_Wkl; }
    else if ((j -= NW4) < NW4)   { in = Wv; hi = g_Wvh; lo = g_Wvl; }
    else if ((j -= NW4) < NW4)   { in = Wo; hi = g_Woh; lo = g_Wol; }
    else return;
    float4 v = ((const float4*)in)[j];
    uint32_t h0, l0, h1, l1;
    split2(v.x, v.y, h0, l0);
    split2(v.z, v.w, h1, l1);
    ((uint2*)hi)[j] = make_uint2(h0, h1);
    ((uint2*)lo)[j] = make_uint2(l0, l1);
}

// ===========================================================================
// bf16x3 GEMM body: C = A[M,K] @ B[N,K]^T  (R9/R11 configuration)
// OMODE 0: fp32 out. OMODE 1: bf16 hi/lo out. OMODE 2: fp16 single out (V).
// ===========================================================================
#define ROWB      80
#define TILE_A    (128 * ROWB)

template<int OMODE, int BNR>
__device__ __forceinline__
void gemm_body(const __nv_bfloat16* __restrict__ Ah, const __nv_bfloat16* __restrict__ Al,
               const __nv_bfloat16* __restrict__ Bh, const __nv_bfloat16* __restrict__ Bl,
               float* __restrict__ C,
               __nv_bfloat16* __restrict__ Ch, __nv_bfloat16* __restrict__ Cl,
               __half* __restrict__ Cf16,
               int M, int N, int K, int bm, int bn, uint32_t sbase)
{
    constexpr int TILE_BB = BNR * ROWB;
    constexpr int BUF_B   = 2 * TILE_A + 2 * TILE_BB;
    constexpr int AHI = 0, ALO = TILE_A, BHI = 2 * TILE_A, BLO = 2 * TILE_A + TILE_BB;
    constexpr int NF = BNR / 16;
    constexpr int NCP = (1024 + BNR * 8) / 256;

    const int tid  = threadIdx.x;
    const int lane = tid & 31;
    const int warp = tid >> 5;
    const int m0 = (warp >> 1) * 32;
    const int n0 = (warp & 1) * (BNR / 2);

    float acc[2][NF][4];
    #pragma unroll
    for (int mt = 0; mt < 2; mt++)
        #pragma unroll
        for (int nf = 0; nf < NF; nf++)
            #pragma unroll
            for (int e = 0; e < 4; e++) acc[mt][nf][e] = 0.0f;

    const int nchunk = K / 32;

    auto issue = [&](int c) {
        const uint32_t buf = sbase + (uint32_t)(c & 1) * BUF_B;
        const int kc = c * 32;
        #pragma unroll
        for (int j = 0; j < NCP; j++) {
            const int idx = tid + j * 256;
            uint32_t dst;
            const __nv_bfloat16* src;
            if (idx < 512) {
                const int row = idx >> 2, ch = idx & 3;
                dst = buf + AHI + row * ROWB + ch * 16;
                src = &Ah[(size_t)(bm + row) * K + kc + ch * 8];
            } else if (idx < 1024) {
                const int r2 = idx - 512;
                const int row = r2 >> 2, ch = r2 & 3;
                dst = buf + ALO + row * ROWB + ch * 16;
                src = &Al[(size_t)(bm + row) * K + kc + ch * 8];
            } else if (idx < 1024 + BNR * 4) {
                const int r2 = idx - 1024;
                const int row = r2 >> 2, ch = r2 & 3;
                dst = buf + BHI + row * ROWB + ch * 16;
                src = &Bh[(size_t)(bn + row) * K + kc + ch * 8];
            } else {
                const int r2 = idx - (1024 + BNR * 4);
                const int row = r2 >> 2, ch = r2 & 3;
                dst = buf + BLO + row * ROWB + ch * 16;
                src = &Bl[(size_t)(bn + row) * K + kc + ch * 8];
            }
            cp_async16(dst, src);
        }
        CP_COMMIT();
    };

    issue(0);

    const uint32_t lrow = (lane & 15);
    const uint32_t koff = (lane >> 4) * 16;

    for (int c = 0; c < nchunk; ++c) {
        CP_WAIT0();
        __syncthreads();
        if (c + 1 < nchunk) issue(c + 1);

        const uint32_t buf = sbase + (uint32_t)(c & 1) * BUF_B;
        #pragma unroll
        for (int ks = 0; ks < 2; ks++) {
            const uint32_t kb = ks * 32 + koff;
            uint32_t ah[2][4], al[2][4];
            #pragma unroll
            for (int mt = 0; mt < 2; mt++) {
                const uint32_t ro = (uint32_t)(m0 + mt * 16 + lrow) * ROWB + kb;
                ldsm_x4(ah[mt], buf + AHI + ro);
                ldsm_x4(al[mt], buf + ALO + ro);
            }
            uint32_t bh[NF / 2][4], bl[NF / 2][4];
            #pragma unroll
            for (int g = 0; g < NF / 2; g++) {
                const uint32_t ro = (uint32_t)(n0 + g * 16 + lrow) * ROWB + kb;
                ldsm_x4(bh[g], buf + BHI + ro);
                ldsm_x4(bl[g], buf + BLO + ro);
            }
            #pragma unroll
            for (int mt = 0; mt < 2; mt++) {
                #pragma unroll
                for (int g = 0; g < NF / 2; g++) {
                    mma_bf16(acc[mt][g * 2 + 0], ah[mt], bh[g][0], bh[g][2]);
                    mma_bf16(acc[mt][g * 2 + 0], ah[mt], bl[g][0], bl[g][2]);
                    mma_bf16(acc[mt][g * 2 + 0], al[mt], bh[g][0], bh[g][2]);
                    mma_bf16(acc[mt][g * 2 + 1], ah[mt], bh[g][1], bh[g][3]);
                    mma_bf16(acc[mt][g * 2 + 1], ah[mt], bl[g][1], bl[g][3]);
                    mma_bf16(acc[mt][g * 2 + 1], al[mt], bh[g][1], bh[g][3]);
                }
            }
        }
        __syncthreads();
    }

    #pragma unroll
    for (int mt = 0; mt < 2; mt++) {
        const int row = bm + m0 + mt * 16 + (lane >> 2);
        #pragma unroll
        for (int nf = 0; nf < NF; nf++) {
            const int col = bn + n0 + nf * 8 + (lane & 3) * 2;
            if (OMODE == 0) {
                *(float2*)&C[(size_t)row * N + col] =
                    make_float2(acc[mt][nf][0], acc[mt][nf][1]);
                *(float2*)&C[(size_t)(row + 8) * N + col] =
                    make_float2(acc[mt][nf][2], acc[mt][nf][3]);
            } else if (OMODE == 1) {
                uint32_t h0, l0, h1, l1;
                split2(acc[mt][nf][0], acc[mt][nf][1], h0, l0);
                split2(acc[mt][nf][2], acc[mt][nf][3], h1, l1);
                *(uint32_t*)&Ch[(size_t)row * N + col]       = h0;
                *(uint32_t*)&Cl[(size_t)row * N + col]       = l0;
                *(uint32_t*)&Ch[(size_t)(row + 8) * N + col] = h1;
                *(uint32_t*)&Cl[(size_t)(row + 8) * N + col] = l1;
            } else {
                *(uint32_t*)&Cf16[(size_t)row * N + col] =
                    pack_h2(acc[mt][nf][0], acc[mt][nf][1]);
                *(uint32_t*)&Cf16[(size_t)(row + 8) * N + col] =
                    pack_h2(acc[mt][nf][2], acc[mt][nf][3]);
            }
        }
    }
}

#define GEMM_SMEM_128 (2 * (2 * TILE_A + 2 * 128 * ROWB))   // 81920
#define GEMM_SMEM_64  (2 * (2 * TILE_A + 2 * 64 * ROWB))    // 61440

// Merged Q/K/V projection: grid (32, 6, 3); z selects operand set.
__global__ __launch_bounds__(256, 2)
void gemm_qkv()
{
    extern __shared__ __align__(128) char dynsm[];
    const uint32_t sbase = smem_u32(dynsm);
    const int z = blockIdx.z;

    if (z == 0) {
        gemm_body<1, 128>(g_xh, g_xl, g_Wqh, g_Wql, nullptr, g_Qh, g_Ql, nullptr,
                          S_LEN, DM, DM, blockIdx.x * 128, blockIdx.y * 128, sbase);
    } else if (z == 1) {
        gemm_body<1, 128>(g_xh, g_xl, g_Wkh, g_Wkl, nullptr, g_Kh, g_Kl, nullptr,
                          S_LEN, DM, DM, blockIdx.x * 128, blockIdx.y * 128, sbase);
    } else {
        // V^T[hd][s] = Wv @ x^T, written as single fp16
        gemm_body<2, 128>(g_Wvh, g_Wvl, g_xh, g_xl, nullptr, nullptr, nullptr, g_Vt,
                          DM, S_LEN, DM, blockIdx.y * 128, blockIdx.x * 128, sbase);
    }
}

// Output projection: out = ctx @ Wo^T (fp32 out), 128x64 tiles, grid (32, 12)
__global__ __launch_bounds__(256, 2)
void gemm_out(float* __restrict__ out)
{
    extern __shared__ __align__(128) char dynsm[];
    const uint32_t sbase = smem_u32(dynsm);
    gemm_body<0, 64>(g_ctxh, g_ctxl, g_Woh, g_Wol, out, nullptr, nullptr, nullptr,
                     S_LEN, DM, DM, blockIdx.x * 128, blockIdx.y * 64, sbase);
}

// ===========================================================================
// Tensor-core causal flash attention.
// QK: bf16x3 (3 mma). PV: single fp16 (1 mma), P rounded to fp16-exact and
// the row-sum l computed from the ROUNDED P -> exact normalization.
// Global LPT CTA order. cp.async double-buffered K(hi/lo)+V(fp16).
// ===========================================================================
#define AROWB 144
#define AQH   0
#define AQL   (128 * AROWB)
#define AKV   (2 * 128 * AROWB)          // 36864
#define KVSTG 24576                      // Kh 8K + Kl 8K + V 8K
#define KH_O  0
#define KL_O  8192
#define V_O   16384
#define ATTN_SMEM (AKV + 2 * KVSTG)      // 86016

__global__ __launch_bounds__(256, 2)
void attn_tc()
{
    extern __shared__ __align__(128) char dynbuf[];
    const uint32_t sb = smem_u32(dynbuf);

    const int tid  = threadIdx.x;
    const int lane = tid & 31;
    const int warp = tid >> 5;
    const int wr   = warp * 16;
    // Global LPT: bid 0..11 -> qb=31 (all heads), bid 12..23 -> qb=30, ...
    const int rank = blockIdx.x;
    const int qb   = (S_LEN / 128) - 1 - rank / NH;
    const int h    = rank % NH;
    const int q0   = qb * 128;

    {
        const int gr = tid >> 3;
        const int gc = tid & 7;
        #pragma unroll
        for (int i = 0; i < 4; i++) {
            const int r = gr + i * 32;
            const uint32_t soff = (uint32_t)r * AROWB + gc * 16;
            uint4 vh = *(const uint4*)&g_Qh[(size_t)(q0 + r) * DM + h * 64 + gc * 8];
            uint4 vl = *(const uint4*)&g_Ql[(size_t)(q0 + r) * DM + h * 64 + gc * 8];
            sts_v4(sb + AQH + soff, vh);
            sts_v4(sb + AQL + soff, vl);
        }
    }

    auto issue_kv = [&](int t) {
        const uint32_t kvb = sb + AKV + (uint32_t)(t & 1) * KVSTG;
        const int k0 = t * 64;
        #pragma unroll
        for (int j = 0; j < 6; j++) {
            const int idx = tid + j * 256;      // 0..1535
            const int arr = idx >> 9;           // 0:Kh 1:Kl 2:V
            const int rem = idx & 511;
            const int row = rem >> 3;
            const int c   = rem & 7;
            const uint32_t dst = kvb + (uint32_t)arr * 8192 + row * 128 +
                                 ((uint32_t)(c ^ (row & 7)) << 4);
            const void* src;
            if (arr == 0)      src = &g_Kh[(size_t)(k0 + row) * DM + h * 64 + c * 8];
            else if (arr == 1) src = &g_Kl[(size_t)(k0 + row) * DM + h * 64 + c * 8];
            else               src = &g_Vt[(size_t)(h * 64 + row) * S_LEN + k0 + c * 8];
            cp_async16(dst, src);
        }
        CP_COMMIT();
    };

    issue_kv(0);

    float o[8][4];
    #pragma unroll
    for (int f = 0; f < 8; f++)
        #pragma unroll
        for (int e = 0; e < 4; e++) o[f][e] = 0.0f;
    float m_s[2] = {-1e30f, -1e30f};
    float l_s[2] = {0.0f, 0.0f};

    const int row0 = q0 + wr + (lane >> 2);
    const int row1 = row0 + 8;
    const uint32_t lrow = (lane & 15);
    const uint32_t koff = (lane >> 4) * 16;
    const int ntile = 2 * qb + 2;

    for (int t = 0; t < ntile; ++t) {
        const int k0 = t * 64;
        CP_WAIT0();
        __syncthreads();
        if (t + 1 < ntile) issue_kv(t + 1);

        const uint32_t kvb = sb + AKV + (uint32_t)(t & 1) * KVSTG;

        float sacc[8][4];
        #pragma unroll
        for (int f = 0; f < 8; f++)
            #pragma unroll
            for (int e = 0; e < 4; e++) sacc[f][e] = 0.0f;

        #pragma unroll
        for (int ks = 0; ks < 4; ks++) {
            uint32_t qh[4], ql[4];
            const uint32_t qoff = (uint32_t)(wr + lrow) * AROWB + ks * 32 + koff;
            ldsm_x4(qh, sb + AQH + qoff);
            ldsm_x4(ql, sb + AQL + qoff);
            const uint32_t cidx = ks * 2 + (lane >> 4);
            #pragma unroll
            for (int g = 0; g < 4; g++) {
                const uint32_t row = g * 16 + lrow;
                const uint32_t ro = row * 128 + ((cidx ^ (row & 7)) << 4);
                uint32_t kh[4], kl[4];
                ldsm_x4(kh, kvb + KH_O + ro);
                ldsm_x4(kl, kvb + KL_O + ro);
                mma_bf16(sacc[g * 2 + 0], qh, kh[0], kh[2]);
                mma_bf16(sacc[g * 2 + 0], qh, kl[0], kl[2]);
                mma_bf16(sacc[g * 2 + 0], ql, kh[0], kh[2]);
                mma_bf16(sacc[g * 2 + 1], qh, kh[1], kh[3]);
                mma_bf16(sacc[g * 2 + 1], qh, kl[1], kl[3]);
                mma_bf16(sacc[g * 2 + 1], ql, kh[1], kh[3]);
            }
        }

        const float scale = 0.125f;
        if (t >= 2 * qb) {
            #pragma unroll
            for (int f = 0; f < 8; f++) {
                const int cb = k0 + f * 8 + (lane & 3) * 2;
                sacc[f][0] = (cb     > row0) ? -1e30f : sacc[f][0] * scale;
                sacc[f][1] = (cb + 1 > row0) ? -1e30f : sacc[f][1] * scale;
                sacc[f][2] = (cb     > row1) ? -1e30f : sacc[f][2] * scale;
                sacc[f][3] = (cb + 1 > row1) ? -1e30f : sacc[f][3] * scale;
            }
        } else {
            #pragma unroll
            for (int f = 0; f < 8; f++)
                #pragma unroll
                for (int e = 0; e < 4; e++) sacc[f][e] *= scale;
        }

        float rm0 = -1e30f, rm1 = -1e30f;
        #pragma unroll
        for (int f = 0; f < 8; f++) {
            rm0 = fmaxf(rm0, fmaxf(sacc[f][0], sacc[f][1]));
            rm1 = fmaxf(rm1, fmaxf(sacc[f][2], sacc[f][3]));
        }
        #pragma unroll
        for (int off = 1; off < 4; off <<= 1) {
            rm0 = fmaxf(rm0, __shfl_xor_sync(0xffffffffu, rm0, off));
            rm1 = fmaxf(rm1, __shfl_xor_sync(0xffffffffu, rm1, off));
        }
        const float mn0 = fmaxf(m_s[0], rm0);
        const float mn1 = fmaxf(m_s[1], rm1);
        const float al0 = __expf(m_s[0] - mn0);
        const float al1 = __expf(m_s[1] - mn1);
        float rs0 = 0.0f, rs1 = 0.0f;
        #pragma unroll
        for (int f = 0; f < 8; f++) {
            // exp, then round to fp16-exact so PV weights == l contribution
            sacc[f][0] = round_h(__expf(sacc[f][0] - mn0));
            sacc[f][1] = round_h(__expf(sacc[f][1] - mn0));
            sacc[f][2] = round_h(__expf(sacc[f][2] - mn1));
            sacc[f][3] = round_h(__expf(sacc[f][3] - mn1));
            rs0 += sacc[f][0] + sacc[f][1];
            rs1 += sacc[f][2] + sacc[f][3];
        }
        #pragma unroll
        for (int off = 1; off < 4; off <<= 1) {
            rs0 += __shfl_xor_sync(0xffffffffu, rs0, off);
            rs1 += __shfl_xor_sync(0xffffffffu, rs1, off);
        }
        l_s[0] = l_s[0] * al0 + rs0;
        l_s[1] = l_s[1] * al1 + rs1;
        m_s[0] = mn0;
        m_s[1] = mn1;
        #pragma unroll
        for (int f = 0; f < 8; f++) {
            o[f][0] *= al0; o[f][1] *= al0;
            o[f][2] *= al1; o[f][3] *= al1;
        }

        // ---- O += P V : single fp16 mma (P already fp16-exact) ----
        #pragma unroll
        for (int ks = 0; ks < 4; ks++) {
            const float* s0 = sacc[2 * ks];
            const float* s1 = sacc[2 * ks + 1];
            uint32_t ph[4];
            ph[0] = pack_h2(s0[0], s0[1]);
            ph[1] = pack_h2(s0[2], s0[3]);
            ph[2] = pack_h2(s1[0], s1[1]);
            ph[3] = pack_h2(s1[2], s1[3]);
            const uint32_t cidx = ks * 2 + (lane >> 4);
            #pragma unroll
            for (int g = 0; g < 4; g++) {
                const uint32_t row = g * 16 + lrow;
                const uint32_t ro = row * 128 + ((cidx ^ (row & 7)) << 4);
                uint32_t vv[4];
                ldsm_x4(vv, kvb + V_O + ro);
                mma_fp16(o[g * 2 + 0], ph, vv[0], vv[2]);
                mma_fp16(o[g * 2 + 1], ph, vv[1], vv[3]);
            }
        }
    }

    const float inv0 = 1.0f / l_s[0];
    const float inv1 = 1.0f / l_s[1];
    #pragma unroll
    for (int f = 0; f < 8; f++) {
        const int col = h * 64 + f * 8 + (lane & 3) * 2;
        uint32_t h0, l0, h1, l1;
        split2(o[f][0] * inv0, o[f][1] * inv0, h0, l0);
        split2(o[f][2] * inv1, o[f][3] * inv1, h1, l1);
        *(uint32_t*)&g_ctxh[(size_t)row0 * DM + col] = h0;
        *(uint32_t*)&g_ctxl[(size_t)row0 * DM + col] = l0;
        *(uint32_t*)&g_ctxh[(size_t)row1 * DM + col] = h1;
        *(uint32_t*)&g_ctxl[(size_t)row1 * DM + col] = l1;
    }
}

// ---------------------------------------------------------------------------
extern "C" void kernel_launch(void* const* d_in, const int* in_sizes, int n_in,
                              void* d_out, int out_size)
{
    const float* x  = (const float*)d_in[0];
    const float* Wq = (const float*)d_in[1];
    const float* Wk = (const float*)d_in[2];
    const float* Wv = (const float*)d_in[3];
    const float* Wo = (const float*)d_in[4];
    float* out = (float*)d_out;

    cudaFuncSetAttribute(gemm_qkv,
                         cudaFuncAttributeMaxDynamicSharedMemorySize, GEMM_SMEM_128);
    cudaFuncSetAttribute(gemm_out,
                         cudaFuncAttributeMaxDynamicSharedMemorySize, GEMM_SMEM_64);
    cudaFuncSetAttribute(attn_tc,
                         cudaFuncAttributeMaxDynamicSharedMemorySize, ATTN_SMEM);

    const int ntot4 = NX4 + 4 * NW4;
    split_all<<<(ntot4 + 255) / 256, 256>>>(x, Wq, Wk, Wv, Wo);

    gemm_qkv<<<dim3(S_LEN / 128, DM / 128, 3), 256, GEMM_SMEM_128>>>();

    attn_tc<<<dim3((S_LEN / 128) * NH), 256, ATTN_SMEM>>>();

    gemm_out<<<dim3(S_LEN / 128, DM / 64), 256, GEMM_SMEM_64>>>(out);
}